// round 4
// baseline (speedup 1.0000x reference)
#include <cuda_runtime.h>
#include <stdint.h>

// Problem constants
#define B_    4096
#define T_    80
#define EMB   100
#define UNITS 512
#define NCOL  2048   // 4 gates * UNITS

// ---------------- device scratch (static allocations only) ----------------
__device__ float g_m0[4 * B_ * EMB];     // per-gate input dropout masks, layer0
__device__ float g_m1[4 * B_ * UNITS];   // per-gate input dropout masks, layer1
__device__ float g_x [T_ * B_ * EMB];    // embedded inputs, [t][b][d]
__device__ float g_h0[B_ * UNITS];
__device__ float g_c0[B_ * UNITS];
__device__ float g_h1[B_ * UNITS];
__device__ float g_c1[B_ * UNITS];
__device__ float g_z [B_ * NCOL];        // gate pre-activations, reused per layer

// ---------------- threefry2x32: FULL 20 rounds (5 groups of 4) ------------
__device__ __forceinline__ uint32_t rotl32(uint32_t x, int d) {
    return (x << d) | (x >> (32 - d));
}

__device__ __forceinline__ void tf2x32(uint32_t k0, uint32_t k1,
                                       uint32_t x0, uint32_t x1,
                                       uint32_t& o0, uint32_t& o1) {
    uint32_t ks0 = k0, ks1 = k1, ks2 = k0 ^ k1 ^ 0x1BD11BDAu;
    x0 += ks0; x1 += ks1;
#define TF_RND(r) { x0 += x1; x1 = rotl32(x1, r); x1 ^= x0; }
    TF_RND(13) TF_RND(15) TF_RND(26) TF_RND(6)
    x0 += ks1; x1 += ks2 + 1u;
    TF_RND(17) TF_RND(29) TF_RND(16) TF_RND(24)
    x0 += ks2; x1 += ks0 + 2u;
    TF_RND(13) TF_RND(15) TF_RND(26) TF_RND(6)
    x0 += ks0; x1 += ks1 + 3u;
    TF_RND(17) TF_RND(29) TF_RND(16) TF_RND(24)
    x0 += ks1; x1 += ks2 + 4u;
    TF_RND(13) TF_RND(15) TF_RND(26) TF_RND(6)   // fifth group (was missing)
    x0 += ks2; x1 += ks0 + 5u;                    // final key injection
#undef TF_RND
    o0 = x0; o1 = x1;
}

// Partitionable-threefry split (JAX >= 0.4.36 default):
// split(key, 2): key_i = threefry2x32(key, hi=0, lo=i), subkey = (o0, o1).
__device__ __forceinline__ void derive_keys(uint32_t& a0, uint32_t& a1,
                                            uint32_t& b0, uint32_t& b1) {
    tf2x32(0u, 42u, 0u, 0u, a0, a1);   // k0
    tf2x32(0u, 42u, 0u, 1u, b0, b1);   // k1
}

__device__ __forceinline__ float bits_to_mask(uint32_t bits) {
    float u = __uint_as_float((bits >> 9) | 0x3f800000u) - 1.0f;
    return (u < 0.8f) ? (1.0f / 0.8f) : 0.0f;
}

// Partitionable random_bits: element i -> (o0,o1)=tf(key, i>>32, i&0xffffffff),
// bits = o0 ^ o1.   which = 0 -> m0 (first split key), 1 -> m1 (second).
__global__ void mask_kernel(float* __restrict__ out, int S, int which) {
    int i = blockIdx.x * blockDim.x + threadIdx.x;
    if (i >= S) return;
    uint32_t a0, a1, b0, b1;
    derive_keys(a0, a1, b0, b1);
    uint32_t k0 = which ? b0 : a0;
    uint32_t k1 = which ? b1 : a1;
    uint32_t o0, o1;
    tf2x32(k0, k1, 0u, (uint32_t)i, o0, o1);
    out[i] = bits_to_mask(o0 ^ o1);
}

// ---------------- embedding gather: g_x[t][b][d] = embed[inputs[b,t], d] ----
__global__ void embed_kernel(const int* __restrict__ inputs,
                             const float* __restrict__ embed) {
    long long idx = (long long)blockIdx.x * blockDim.x + threadIdx.x;
    if (idx >= (long long)T_ * B_ * EMB) return;
    int d = (int)(idx % EMB);
    int b = (int)((idx / EMB) % B_);
    int t = (int)(idx / ((long long)EMB * B_));
    int tok = inputs[b * T_ + t];
    g_x[idx] = embed[(long long)tok * EMB + d];
}

__global__ void init_states_kernel() {
    int i = blockIdx.x * blockDim.x + threadIdx.x;
    if (i >= B_ * UNITS) return;
    g_h0[i] = 0.f; g_c0[i] = 0.f; g_h1[i] = 0.f; g_c1[i] = 0.f;
}

// ---------------- fused gate GEMM ----------------
// z[b, g*512+h] = sum_k xin[b,k]*mask[g,b,k]*Wx[k, g*512+h]
//              + sum_k hst[b,k]*U[k, g*512+h] + bias[g*512+h]
// BM=BN=128, BK=8, 256 threads, 8x8 per-thread tile.
#define BM 128
#define BN 128
#define BK 8

__global__ __launch_bounds__(256)
void gate_gemm(const float* __restrict__ xin, int Kx,
               const float* __restrict__ mask,   // [4, B, Kx]
               const float* __restrict__ Wx,     // [Kx, 2048]
               const float* __restrict__ hst,    // [B, 512]
               const float* __restrict__ U,      // [512, 2048]
               const float* __restrict__ bias,   // [2048]
               float* __restrict__ z)            // [B, 2048]
{
    __shared__ float As[BK][BM + 4];
    __shared__ float Bs[BK][BN + 4];

    const int tid  = threadIdx.x;
    const int m0   = blockIdx.y * BM;
    const int n0   = blockIdx.x * BN;
    const int gate = n0 / UNITS;

    const int tx = tid & 15;        // 0..15 -> 8 cols each
    const int ty = tid >> 4;        // 0..15 -> 8 rows each
    const int lk = tid & 7;         // A-load k
    const int lm = tid >> 3;        // A-load row (0..31)
    const int ln = tid & 127;       // B-load col
    const int lkb = tid >> 7;       // B-load k (0..1)

    float acc[8][8];
#pragma unroll
    for (int i = 0; i < 8; i++)
#pragma unroll
        for (int j = 0; j < 8; j++) acc[i][j] = 0.f;

    // -------- phase 1: masked x part, K = Kx (ragged) --------
    const int kx_tiles = (Kx + BK - 1) / BK;
    for (int kt = 0; kt < kx_tiles; ++kt) {
        const int kbase = kt * BK;
#pragma unroll
        for (int p = 0; p < 4; p++) {
            int m = lm + p * 32;
            int k = kbase + lk;
            float v = 0.f;
            if (k < Kx) {
                int b = m0 + m;
                v = xin[b * Kx + k] * mask[(gate * B_ + b) * Kx + k];
            }
            As[lk][m] = v;
        }
#pragma unroll
        for (int p = 0; p < 4; p++) {
            int kk = lkb + p * 2;
            int k = kbase + kk;
            Bs[kk][ln] = (k < Kx) ? Wx[k * NCOL + n0 + ln] : 0.f;
        }
        __syncthreads();
#pragma unroll
        for (int k = 0; k < BK; k++) {
            float4 av0 = *(const float4*)&As[k][ty * 8];
            float4 av1 = *(const float4*)&As[k][ty * 8 + 4];
            float4 bv0 = *(const float4*)&Bs[k][tx * 8];
            float4 bv1 = *(const float4*)&Bs[k][tx * 8 + 4];
            float a[8] = {av0.x, av0.y, av0.z, av0.w, av1.x, av1.y, av1.z, av1.w};
            float bb[8] = {bv0.x, bv0.y, bv0.z, bv0.w, bv1.x, bv1.y, bv1.z, bv1.w};
#pragma unroll
            for (int i = 0; i < 8; i++)
#pragma unroll
                for (int j = 0; j < 8; j++) acc[i][j] += a[i] * bb[j];
        }
        __syncthreads();
    }

    // -------- phase 2: recurrent part, K = 512 (no guards) --------
    for (int kt = 0; kt < UNITS / BK; ++kt) {
        const int kbase = kt * BK;
#pragma unroll
        for (int p = 0; p < 4; p++) {
            int m = lm + p * 32;
            As[lk][m] = hst[(m0 + m) * UNITS + kbase + lk];
        }
#pragma unroll
        for (int p = 0; p < 4; p++) {
            int kk = lkb + p * 2;
            Bs[kk][ln] = U[(kbase + kk) * NCOL + n0 + ln];
        }
        __syncthreads();
#pragma unroll
        for (int k = 0; k < BK; k++) {
            float4 av0 = *(const float4*)&As[k][ty * 8];
            float4 av1 = *(const float4*)&As[k][ty * 8 + 4];
            float4 bv0 = *(const float4*)&Bs[k][tx * 8];
            float4 bv1 = *(const float4*)&Bs[k][tx * 8 + 4];
            float a[8] = {av0.x, av0.y, av0.z, av0.w, av1.x, av1.y, av1.z, av1.w};
            float bb[8] = {bv0.x, bv0.y, bv0.z, bv0.w, bv1.x, bv1.y, bv1.z, bv1.w};
#pragma unroll
            for (int i = 0; i < 8; i++)
#pragma unroll
                for (int j = 0; j < 8; j++) acc[i][j] += a[i] * bb[j];
        }
        __syncthreads();
    }

    // -------- epilogue: + bias, store z --------
#pragma unroll
    for (int i = 0; i < 8; i++) {
        int row = m0 + ty * 8 + i;
#pragma unroll
        for (int j = 0; j < 8; j++) {
            int col = n0 + tx * 8 + j;
            z[row * NCOL + col] = acc[i][j] + bias[col];
        }
    }
}

// ---------------- LSTM pointwise: gates -> h,c update ----------------
__device__ __forceinline__ float sigmoidf_(float x) {
    return 1.0f / (1.0f + expf(-x));
}

__global__ void lstm_pointwise(const float* __restrict__ z,
                               float* __restrict__ h, float* __restrict__ c) {
    int idx = blockIdx.x * blockDim.x + threadIdx.x;
    if (idx >= B_ * UNITS) return;
    int b = idx / UNITS;
    int u = idx % UNITS;
    const float* zb = z + b * NCOL;
    float ig = sigmoidf_(zb[u]);
    float fg = sigmoidf_(zb[UNITS + u]);
    float gg = tanhf(zb[2 * UNITS + u]);
    float og = sigmoidf_(zb[3 * UNITS + u]);
    float cn = fg * c[idx] + ig * gg;
    c[idx] = cn;
    h[idx] = og * tanhf(cn);
}

// ---------------- final projection: sigmoid(h1 @ Wout + bout) ----------
__global__ void out_kernel(const float* __restrict__ Wout,
                           const float* __restrict__ bout,
                           float* __restrict__ out) {
    int warps_per_block = blockDim.x / 32;
    int b = blockIdx.x * warps_per_block + (threadIdx.x >> 5);
    int lane = threadIdx.x & 31;
    if (b >= B_) return;
    float s = 0.f;
    for (int k = lane; k < UNITS; k += 32)
        s += g_h1[b * UNITS + k] * Wout[k];
#pragma unroll
    for (int off = 16; off; off >>= 1)
        s += __shfl_down_sync(0xffffffffu, s, off);
    if (lane == 0)
        out[b] = sigmoidf_(s + bout[0]);
}

// ---------------- launch ----------------
extern "C" void kernel_launch(void* const* d_in, const int* in_sizes, int n_in,
                              void* d_out, int out_size) {
    const int*   inputs = (const int*)  d_in[0];
    const float* embed  = (const float*)d_in[1];
    const float* W0     = (const float*)d_in[2];
    const float* U0     = (const float*)d_in[3];
    const float* b0     = (const float*)d_in[4];
    const float* W1     = (const float*)d_in[5];
    const float* U1     = (const float*)d_in[6];
    const float* b1     = (const float*)d_in[7];
    const float* Wout   = (const float*)d_in[8];
    const float* bout   = (const float*)d_in[9];
    float* out = (float*)d_out;

    float *m0p, *m1p, *xp, *h0p, *c0p, *h1p, *c1p, *zp;
    cudaGetSymbolAddress((void**)&m0p, g_m0);
    cudaGetSymbolAddress((void**)&m1p, g_m1);
    cudaGetSymbolAddress((void**)&xp,  g_x);
    cudaGetSymbolAddress((void**)&h0p, g_h0);
    cudaGetSymbolAddress((void**)&c0p, g_c0);
    cudaGetSymbolAddress((void**)&h1p, g_h1);
    cudaGetSymbolAddress((void**)&c1p, g_c1);
    cudaGetSymbolAddress((void**)&zp,  g_z);

    // init states
    init_states_kernel<<<(B_ * UNITS + 255) / 256, 256>>>();

    // dropout masks (exact threefry-20, partitionable scheme)
    {
        int S0 = 4 * B_ * EMB;
        int S1 = 4 * B_ * UNITS;
        mask_kernel<<<(S0 + 255) / 256, 256>>>(m0p, S0, 0);
        mask_kernel<<<(S1 + 255) / 256, 256>>>(m1p, S1, 1);
    }

    // embeddings -> [t][b][d]
    {
        long long tot = (long long)T_ * B_ * EMB;
        embed_kernel<<<(unsigned)((tot + 255) / 256), 256>>>(inputs, embed);
    }

    dim3 ggrid(NCOL / BN, B_ / BM);   // (16, 32)
    int pw_blocks = (B_ * UNITS + 255) / 256;

    for (int t = 0; t < T_; ++t) {
        // layer 0: x = embedded token, Kx = 100
        gate_gemm<<<ggrid, 256>>>(xp + (long long)t * B_ * EMB, EMB,
                                  m0p, W0, h0p, U0, b0, zp);
        lstm_pointwise<<<pw_blocks, 256>>>(zp, h0p, c0p);
        // layer 1: x = new h0, Kx = 512
        gate_gemm<<<ggrid, 256>>>(h0p, UNITS,
                                  m1p, W1, h1p, U1, b1, zp);
        lstm_pointwise<<<pw_blocks, 256>>>(zp, h1p, c1p);
    }

    out_kernel<<<B_ / 8, 256>>>(Wout, bout, out);
}

// round 6
// speedup vs baseline: 2.4134x; 2.4134x over previous
#include <cuda_runtime.h>
#include <stdint.h>

// Problem constants
#define B_    4096
#define T_    80
#define EMB   100
#define UNITS 512
#define NCOL  2048   // 4 gates * UNITS

#define KXP0  128    // EMB padded to multiple of 32

// ---------------- device scratch (static allocations only) ----------------
__device__ float g_m0[4 * B_ * EMB];
__device__ float g_m1[4 * B_ * UNITS];
__device__ float g_x [T_ * B_ * EMB];
__device__ float g_h0[B_ * UNITS];
__device__ float g_c0[B_ * UNITS];
__device__ float g_h1[B_ * UNITS];
__device__ float g_c1[B_ * UNITS];
__device__ float g_z [B_ * NCOL];
// transposed + tf32-rounded weights, layout [n][k]
__device__ float g_wt0[NCOL * KXP0];
__device__ float g_ut0[NCOL * UNITS];
__device__ float g_wt1[NCOL * UNITS];
__device__ float g_ut1[NCOL * UNITS];

// ---------------- tf32 round ----------------
__device__ __forceinline__ float tf32r(float x) {
    float r;
    asm("cvt.rna.tf32.f32 %0, %1;" : "=f"(r) : "f"(x));
    return r;
}

// ---------------- threefry2x32 (full 20 rounds) ----------------
__device__ __forceinline__ uint32_t rotl32(uint32_t x, int d) {
    return (x << d) | (x >> (32 - d));
}

__device__ __forceinline__ void tf2x32(uint32_t k0, uint32_t k1,
                                       uint32_t x0, uint32_t x1,
                                       uint32_t& o0, uint32_t& o1) {
    uint32_t ks0 = k0, ks1 = k1, ks2 = k0 ^ k1 ^ 0x1BD11BDAu;
    x0 += ks0; x1 += ks1;
#define TF_RND(r) { x0 += x1; x1 = rotl32(x1, r); x1 ^= x0; }
    TF_RND(13) TF_RND(15) TF_RND(26) TF_RND(6)
    x0 += ks1; x1 += ks2 + 1u;
    TF_RND(17) TF_RND(29) TF_RND(16) TF_RND(24)
    x0 += ks2; x1 += ks0 + 2u;
    TF_RND(13) TF_RND(15) TF_RND(26) TF_RND(6)
    x0 += ks0; x1 += ks1 + 3u;
    TF_RND(17) TF_RND(29) TF_RND(16) TF_RND(24)
    x0 += ks1; x1 += ks2 + 4u;
    TF_RND(13) TF_RND(15) TF_RND(26) TF_RND(6)
    x0 += ks2; x1 += ks0 + 5u;
#undef TF_RND
    o0 = x0; o1 = x1;
}

__device__ __forceinline__ void derive_keys(uint32_t& a0, uint32_t& a1,
                                            uint32_t& b0, uint32_t& b1) {
    tf2x32(0u, 42u, 0u, 0u, a0, a1);
    tf2x32(0u, 42u, 0u, 1u, b0, b1);
}

__device__ __forceinline__ float bits_to_mask(uint32_t bits) {
    float u = __uint_as_float((bits >> 9) | 0x3f800000u) - 1.0f;
    return (u < 0.8f) ? (1.0f / 0.8f) : 0.0f;
}

__global__ void mask_kernel(float* __restrict__ out, int S, int which) {
    int i = blockIdx.x * blockDim.x + threadIdx.x;
    if (i >= S) return;
    uint32_t a0, a1, b0, b1;
    derive_keys(a0, a1, b0, b1);
    uint32_t k0 = which ? b0 : a0;
    uint32_t k1 = which ? b1 : a1;
    uint32_t o0, o1;
    tf2x32(k0, k1, 0u, (uint32_t)i, o0, o1);
    out[i] = bits_to_mask(o0 ^ o1);
}

// ---------------- embedding gather ----------------
__global__ void embed_kernel(const int* __restrict__ inputs,
                             const float* __restrict__ embed) {
    long long idx = (long long)blockIdx.x * blockDim.x + threadIdx.x;
    if (idx >= (long long)T_ * B_ * EMB) return;
    int d = (int)(idx % EMB);
    int b = (int)((idx / EMB) % B_);
    int t = (int)(idx / ((long long)EMB * B_));
    int tok = inputs[b * T_ + t];
    g_x[idx] = embed[(long long)tok * EMB + d];
}

__global__ void init_states_kernel() {
    int i = blockIdx.x * blockDim.x + threadIdx.x;
    if (i >= B_ * UNITS) return;
    g_h0[i] = 0.f; g_c0[i] = 0.f; g_h1[i] = 0.f; g_c1[i] = 0.f;
}

// ---------------- weight transpose + tf32 round: Wt[n][k] = W[k][n] --------
__global__ void wtrans_kernel(const float* __restrict__ W,
                              float* __restrict__ Wt, int Kreal, int Kxp) {
    long long idx = (long long)blockIdx.x * blockDim.x + threadIdx.x;
    if (idx >= (long long)NCOL * Kxp) return;
    int k = (int)(idx % Kxp);
    int n = (int)(idx / Kxp);
    float v = (k < Kreal) ? W[(size_t)k * NCOL + n] : 0.f;
    Wt[idx] = tf32r(v);
}

// ---------------- tensor-core gate GEMM (mma.sync tf32) ----------------
// z[128, 128 tile] = (xin*mask_g) @ W + hst @ U + bias
// CTA: 256 threads = 8 warps (4 M x 2 N); warp tile 32x64;
// mma m16n8k8 tf32; K chunk 32; smem stride 36 floats (conflict-free).
#define SSTR 36

__device__ __forceinline__ void mma_tf32(float* c, uint32_t a0, uint32_t a1,
                                         uint32_t a2, uint32_t a3,
                                         uint32_t b0, uint32_t b1) {
    asm volatile(
        "mma.sync.aligned.m16n8k8.row.col.f32.tf32.tf32.f32 "
        "{%0,%1,%2,%3}, {%4,%5,%6,%7}, {%8,%9}, {%0,%1,%2,%3};"
        : "+f"(c[0]), "+f"(c[1]), "+f"(c[2]), "+f"(c[3])
        : "r"(a0), "r"(a1), "r"(a2), "r"(a3), "r"(b0), "r"(b1));
}

__global__ __launch_bounds__(256, 2)
void gate_gemm_mma(const float* __restrict__ xin, int Kreal, int Kxp,
                   const float* __restrict__ mask,   // [4, B, Kreal]
                   const float* __restrict__ Wt,     // [2048][Kxp] tf32
                   const float* __restrict__ hst,    // [B, 512]
                   const float* __restrict__ Ut,     // [2048][512] tf32
                   const float* __restrict__ bias,
                   float* __restrict__ z)
{
    __shared__ float As[128 * SSTR];
    __shared__ float Bs[128 * SSTR];

    const int tid  = threadIdx.x;
    const int wid  = tid >> 5;
    const int lane = tid & 31;
    const int wm   = wid & 3;          // warp M block (32 rows)
    const int wn   = wid >> 2;         // warp N block (64 cols)
    const int gq   = lane >> 2;        // group id 0..7
    const int gt   = lane & 3;         // thread-in-group 0..3

    const int m0v = blockIdx.y * 128;
    const int n0  = blockIdx.x * 128;
    const int gate = n0 >> 9;
    const float* maskg = mask + (size_t)gate * B_ * Kreal;

    float acc[2][8][4];
#pragma unroll
    for (int mt = 0; mt < 2; mt++)
#pragma unroll
        for (int nt = 0; nt < 8; nt++)
#pragma unroll
            for (int e = 0; e < 4; e++) acc[mt][nt][e] = 0.f;

    const int nch0 = Kxp >> 5;
    const int ncht = nch0 + (UNITS >> 5);

    const int lrow  = tid >> 1;          // 0..127
    const int lhalf = (tid & 1) * 16;    // 0 or 16

    for (int ic = 0; ic < ncht; ++ic) {
        const bool p0 = (ic < nch0);
        const int kbase = p0 ? (ic << 5) : ((ic - nch0) << 5);

        // ---- A tile: 128 rows x 32 k ----
        {
            const float* asrc = p0 ? xin : hst;
            const int astride = p0 ? Kreal : UNITS;
            const int alim    = p0 ? Kreal : UNITS;
            const size_t rbase = (size_t)(m0v + lrow) * astride;
            float* dst = &As[lrow * SSTR + lhalf];
#pragma unroll
            for (int jj = 0; jj < 4; jj++) {
                int k4 = kbase + lhalf + jj * 4;
                float4 v = make_float4(0.f, 0.f, 0.f, 0.f);
                if (k4 < alim) {
                    v = *(const float4*)(asrc + rbase + k4);
                    if (p0) {
                        float4 m = *(const float4*)(maskg + (size_t)(m0v + lrow) * Kreal + k4);
                        v.x *= m.x; v.y *= m.y; v.z *= m.z; v.w *= m.w;
                    }
                    v.x = tf32r(v.x); v.y = tf32r(v.y);
                    v.z = tf32r(v.z); v.w = tf32r(v.w);
                }
                *(float4*)(dst + jj * 4) = v;
            }
        }
        // ---- B tile: 128 n-rows x 32 k (pre-transposed, pre-rounded) ----
        {
            const float* bsrc = p0 ? Wt : Ut;
            const int bstride = p0 ? Kxp : UNITS;
            const size_t rbase = (size_t)(n0 + lrow) * bstride + kbase + lhalf;
            float* dst = &Bs[lrow * SSTR + lhalf];
#pragma unroll
            for (int jj = 0; jj < 4; jj++)
                *(float4*)(dst + jj * 4) = *(const float4*)(bsrc + rbase + jj * 4);
        }
        __syncthreads();

        // ---- compute: 4 k8 steps ----
#pragma unroll
        for (int ks = 0; ks < 4; ks++) {
            uint32_t bf[8][2];
#pragma unroll
            for (int nt = 0; nt < 8; nt++) {
                int n = wn * 64 + nt * 8 + gq;
                bf[nt][0] = __float_as_uint(Bs[n * SSTR + ks * 8 + gt]);
                bf[nt][1] = __float_as_uint(Bs[n * SSTR + ks * 8 + gt + 4]);
            }
#pragma unroll
            for (int mt = 0; mt < 2; mt++) {
                int m = wm * 32 + mt * 16 + gq;
                uint32_t a0 = __float_as_uint(As[m * SSTR + ks * 8 + gt]);
                uint32_t a1 = __float_as_uint(As[(m + 8) * SSTR + ks * 8 + gt]);
                uint32_t a2 = __float_as_uint(As[m * SSTR + ks * 8 + gt + 4]);
                uint32_t a3 = __float_as_uint(As[(m + 8) * SSTR + ks * 8 + gt + 4]);
#pragma unroll
                for (int nt = 0; nt < 8; nt++)
                    mma_tf32(acc[mt][nt], a0, a1, a2, a3, bf[nt][0], bf[nt][1]);
            }
        }
        __syncthreads();
    }

    // ---- epilogue: + bias, store z ----
#pragma unroll
    for (int mt = 0; mt < 2; mt++) {
        int row0 = m0v + wm * 32 + mt * 16 + gq;
#pragma unroll
        for (int nt = 0; nt < 8; nt++) {
            int col = n0 + wn * 64 + nt * 8 + gt * 2;
            float b0v = bias[col], b1v = bias[col + 1];
            float2 v0 = make_float2(acc[mt][nt][0] + b0v, acc[mt][nt][1] + b1v);
            float2 v1 = make_float2(acc[mt][nt][2] + b0v, acc[mt][nt][3] + b1v);
            *(float2*)(z + (size_t)row0 * NCOL + col) = v0;
            *(float2*)(z + (size_t)(row0 + 8) * NCOL + col) = v1;
        }
    }
}

// ---------------- LSTM pointwise ----------------
__device__ __forceinline__ float sigmoidf_(float x) {
    return 1.0f / (1.0f + expf(-x));
}

__global__ void lstm_pointwise(const float* __restrict__ z,
                               float* __restrict__ h, float* __restrict__ c) {
    int idx = blockIdx.x * blockDim.x + threadIdx.x;
    if (idx >= B_ * UNITS) return;
    int b = idx / UNITS;
    int u = idx % UNITS;
    const float* zb = z + (size_t)b * NCOL;
    float ig = sigmoidf_(zb[u]);
    float fg = sigmoidf_(zb[UNITS + u]);
    float gg = tanhf(zb[2 * UNITS + u]);
    float og = sigmoidf_(zb[3 * UNITS + u]);
    float cn = fg * c[idx] + ig * gg;
    c[idx] = cn;
    h[idx] = og * tanhf(cn);
}

// ---------------- final projection ----------------
__global__ void out_kernel(const float* __restrict__ Wout,
                           const float* __restrict__ bout,
                           float* __restrict__ out) {
    int warps_per_block = blockDim.x / 32;
    int b = blockIdx.x * warps_per_block + (threadIdx.x >> 5);
    int lane = threadIdx.x & 31;
    if (b >= B_) return;
    float s = 0.f;
    for (int k = lane; k < UNITS; k += 32)
        s += g_h1[b * UNITS + k] * Wout[k];
#pragma unroll
    for (int off = 16; off; off >>= 1)
        s += __shfl_down_sync(0xffffffffu, s, off);
    if (lane == 0)
        out[b] = sigmoidf_(s + bout[0]);
}

// ---------------- launch ----------------
extern "C" void kernel_launch(void* const* d_in, const int* in_sizes, int n_in,
                              void* d_out, int out_size) {
    const int*   inputs = (const int*)  d_in[0];
    const float* embed  = (const float*)d_in[1];
    const float* W0     = (const float*)d_in[2];
    const float* U0     = (const float*)d_in[3];
    const float* b0     = (const float*)d_in[4];
    const float* W1     = (const float*)d_in[5];
    const float* U1     = (const float*)d_in[6];
    const float* b1     = (const float*)d_in[7];
    const float* Wout   = (const float*)d_in[8];
    const float* bout   = (const float*)d_in[9];
    float* out = (float*)d_out;

    float *m0p, *m1p, *xp, *h0p, *c0p, *h1p, *c1p, *zp;
    float *wt0, *ut0, *wt1, *ut1;
    cudaGetSymbolAddress((void**)&m0p, g_m0);
    cudaGetSymbolAddress((void**)&m1p, g_m1);
    cudaGetSymbolAddress((void**)&xp,  g_x);
    cudaGetSymbolAddress((void**)&h0p, g_h0);
    cudaGetSymbolAddress((void**)&c0p, g_c0);
    cudaGetSymbolAddress((void**)&h1p, g_h1);
    cudaGetSymbolAddress((void**)&c1p, g_c1);
    cudaGetSymbolAddress((void**)&zp,  g_z);
    cudaGetSymbolAddress((void**)&wt0, g_wt0);
    cudaGetSymbolAddress((void**)&ut0, g_ut0);
    cudaGetSymbolAddress((void**)&wt1, g_wt1);
    cudaGetSymbolAddress((void**)&ut1, g_ut1);

    init_states_kernel<<<(B_ * UNITS + 255) / 256, 256>>>();

    {
        int S0 = 4 * B_ * EMB;
        int S1 = 4 * B_ * UNITS;
        mask_kernel<<<(S0 + 255) / 256, 256>>>(m0p, S0, 0);
        mask_kernel<<<(S1 + 255) / 256, 256>>>(m1p, S1, 1);
    }
    {
        long long tot = (long long)T_ * B_ * EMB;
        embed_kernel<<<(unsigned)((tot + 255) / 256), 256>>>(inputs, embed);
    }

    // pre-transpose + tf32-round weights
    wtrans_kernel<<<(NCOL * KXP0  + 255) / 256, 256>>>(W0, wt0, EMB,   KXP0);
    wtrans_kernel<<<(NCOL * UNITS + 255) / 256, 256>>>(U0, ut0, UNITS, UNITS);
    wtrans_kernel<<<(NCOL * UNITS + 255) / 256, 256>>>(W1, wt1, UNITS, UNITS);
    wtrans_kernel<<<(NCOL * UNITS + 255) / 256, 256>>>(U1, ut1, UNITS, UNITS);

    dim3 ggrid(NCOL / 128, B_ / 128);   // (16, 32)
    int pw_blocks = (B_ * UNITS + 255) / 256;

    for (int t = 0; t < T_; ++t) {
        gate_gemm_mma<<<ggrid, 256>>>(
            xp + (long long)t * B_ * EMB, EMB, KXP0,
            m0p, wt0, h0p, ut0, b0, zp);
        lstm_pointwise<<<pw_blocks, 256>>>(zp, h0p, c0p);
        gate_gemm_mma<<<ggrid, 256>>>(
            h0p, UNITS, UNITS,
            m1p, wt1, h1p, ut1, b1, zp);
        lstm_pointwise<<<pw_blocks, 256>>>(zp, h1p, c1p);
    }

    out_kernel<<<B_ / 8, 256>>>(Wout, bout, out);
}

// round 9
// speedup vs baseline: 4.1450x; 1.7175x over previous
#include <cuda_runtime.h>
#include <cuda_bf16.h>
#include <stdint.h>

// Problem constants
#define B_    4096
#define T_    80
#define EMB   100
#define EMBP  128    // EMB padded to k-chunk multiple
#define UNITS 512
#define NCOL  2048   // 4 gates * UNITS

// ---------------- device scratch (static allocations only) ----------------
__device__ float g_m0[4 * B_ * EMB];            // layer0 input dropout masks
__device__ float g_m1[4 * B_ * UNITS];          // layer1 input dropout masks
__device__ __nv_bfloat16 g_xm[(size_t)T_ * 4 * B_ * EMBP]; // x*m0, bf16, [t][g][b][k]
__device__ float g_c0[B_ * UNITS];
__device__ float g_c1[B_ * UNITS];
__device__ float g_h1f[B_ * UNITS];             // fp32 h1 for output projection
__device__ __nv_bfloat16 g_h0b[B_ * UNITS];     // h0 unmasked bf16 (U0 operand)
__device__ __nv_bfloat16 g_h1b[B_ * UNITS];     // h1 unmasked bf16 (U1 operand)
__device__ __nv_bfloat16 g_h0m[4 * B_ * UNITS]; // h0 * m1[g], bf16 (W1 operand)
__device__ float g_z [B_ * NCOL];
// bf16 weights, transposed to [n][k]
__device__ __nv_bfloat16 g_wt0[NCOL * EMBP];
__device__ __nv_bfloat16 g_ut0[NCOL * UNITS];
__device__ __nv_bfloat16 g_wt1[NCOL * UNITS];
__device__ __nv_bfloat16 g_ut1[NCOL * UNITS];

// ---------------- threefry2x32 (full 20 rounds) ----------------
__device__ __forceinline__ uint32_t rotl32(uint32_t x, int d) {
    return (x << d) | (x >> (32 - d));
}

__device__ __forceinline__ void tf2x32(uint32_t k0, uint32_t k1,
                                       uint32_t x0, uint32_t x1,
                                       uint32_t& o0, uint32_t& o1) {
    uint32_t ks0 = k0, ks1 = k1, ks2 = k0 ^ k1 ^ 0x1BD11BDAu;
    x0 += ks0; x1 += ks1;
#define TF_RND(r) { x0 += x1; x1 = rotl32(x1, r); x1 ^= x0; }
    TF_RND(13) TF_RND(15) TF_RND(26) TF_RND(6)
    x0 += ks1; x1 += ks2 + 1u;
    TF_RND(17) TF_RND(29) TF_RND(16) TF_RND(24)
    x0 += ks2; x1 += ks0 + 2u;
    TF_RND(13) TF_RND(15) TF_RND(26) TF_RND(6)
    x0 += ks0; x1 += ks1 + 3u;
    TF_RND(17) TF_RND(29) TF_RND(16) TF_RND(24)
    x0 += ks1; x1 += ks2 + 4u;
    TF_RND(13) TF_RND(15) TF_RND(26) TF_RND(6)
    x0 += ks2; x1 += ks0 + 5u;
#undef TF_RND
    o0 = x0; o1 = x1;
}

__device__ __forceinline__ void derive_keys(uint32_t& a0, uint32_t& a1,
                                            uint32_t& b0, uint32_t& b1) {
    tf2x32(0u, 42u, 0u, 0u, a0, a1);
    tf2x32(0u, 42u, 0u, 1u, b0, b1);
}

__device__ __forceinline__ float bits_to_mask(uint32_t bits) {
    float u = __uint_as_float((bits >> 9) | 0x3f800000u) - 1.0f;
    return (u < 0.8f) ? (1.0f / 0.8f) : 0.0f;
}

__global__ void mask_kernel(float* __restrict__ out, int S, int which) {
    int i = blockIdx.x * blockDim.x + threadIdx.x;
    if (i >= S) return;
    uint32_t a0, a1, b0, b1;
    derive_keys(a0, a1, b0, b1);
    uint32_t k0 = which ? b0 : a0;
    uint32_t k1 = which ? b1 : a1;
    uint32_t o0, o1;
    tf2x32(k0, k1, 0u, (uint32_t)i, o0, o1);
    out[i] = bits_to_mask(o0 ^ o1);
}

// ---------------- precompute x*m0 in bf16: [t][g][b][k] ----------------
__global__ void xm_kernel(const int* __restrict__ inputs,
                          const float* __restrict__ embed) {
    size_t idx = (size_t)blockIdx.x * blockDim.x + threadIdx.x;
    if (idx >= (size_t)T_ * 4 * B_ * EMBP) return;
    int k = (int)(idx & 127);
    int b = (int)((idx >> 7) & 4095);
    int g = (int)((idx >> 19) & 3);
    int t = (int)(idx >> 21);
    float v = 0.f;
    if (k < EMB) {
        int tok = inputs[b * T_ + t];
        v = embed[(size_t)tok * EMB + k] * g_m0[((size_t)g * B_ + b) * EMB + k];
    }
    g_xm[idx] = __float2bfloat16(v);
}

__global__ void init_states_kernel() {
    int i = blockIdx.x * blockDim.x + threadIdx.x;
    if (i >= B_ * UNITS) return;
    g_c0[i] = 0.f; g_c1[i] = 0.f; g_h1f[i] = 0.f;
    __nv_bfloat16 zb = __float2bfloat16(0.f);
    g_h0b[i] = zb; g_h1b[i] = zb;
#pragma unroll
    for (int g = 0; g < 4; g++) g_h0m[g * B_ * UNITS + i] = zb;
}

// ---------------- weight transpose + bf16: Wt[n][k] = bf16(W[k][n]) --------
__global__ void wtrans_kernel(const float* __restrict__ W,
                              __nv_bfloat16* __restrict__ Wt,
                              int Kreal, int Kp) {
    size_t idx = (size_t)blockIdx.x * blockDim.x + threadIdx.x;
    if (idx >= (size_t)NCOL * Kp) return;
    int k = (int)(idx % Kp);
    int n = (int)(idx / Kp);
    float v = (k < Kreal) ? W[(size_t)k * NCOL + n] : 0.f;
    Wt[idx] = __float2bfloat16(v);
}

// ---------------- bf16 tensor-core gate GEMM, cp.async double-buffered -----
// CTA tile 128x128, 256 threads (8 warps = 4M x 2N), warp tile 32x64,
// mma m16n8k16 bf16, K-chunk 64, smem stride 72 bf16 (144B, 16B-aligned,
// conflict-free fragment LDS).
// SMEM layout per buffer: A tile (128*144B = 18432B) then B tile (18432B).
// Buffer b starts at offset b * 36864.
#define KC    64
#define SSTRB 72
#define TILE1 18432          // one tile (A or B), bytes
#define BUFSZ (2 * TILE1)    // A + B per buffer

__device__ __forceinline__ void cpasync16(uint32_t dst, const void* src) {
    asm volatile("cp.async.cg.shared.global [%0], [%1], 16;"
                 :: "r"(dst), "l"(src) : "memory");
}

__device__ __forceinline__ void mma_bf16(float* c, uint32_t a0, uint32_t a1,
                                         uint32_t a2, uint32_t a3,
                                         uint32_t b0, uint32_t b1) {
    asm volatile(
        "mma.sync.aligned.m16n8k16.row.col.f32.bf16.bf16.f32 "
        "{%0,%1,%2,%3}, {%4,%5,%6,%7}, {%8,%9}, {%0,%1,%2,%3};"
        : "+f"(c[0]), "+f"(c[1]), "+f"(c[2]), "+f"(c[3])
        : "r"(a0), "r"(a1), "r"(a2), "r"(a3), "r"(b0), "r"(b1));
}

__global__ __launch_bounds__(256, 2)
void gate_gemm_bf16(const __nv_bfloat16* __restrict__ a1, int k1, int n1,
                    size_t a1_gate_stride,
                    const __nv_bfloat16* __restrict__ a2,   // [B][512]
                    const __nv_bfloat16* __restrict__ bt1,  // [2048][k1]
                    const __nv_bfloat16* __restrict__ bt2,  // [2048][512]
                    const float* __restrict__ bias,
                    float* __restrict__ z)
{
    extern __shared__ char dsm[];
    uint32_t smem_base;
    asm("{ .reg .u64 t; cvta.to.shared.u64 t, %1; cvt.u32.u64 %0, t; }"
        : "=r"(smem_base) : "l"(dsm));

    const int tid  = threadIdx.x;
    const int wid  = tid >> 5;
    const int lane = tid & 31;
    const int wm   = wid & 3;
    const int wn   = wid >> 2;
    const int gq   = lane >> 2;
    const int gt   = lane & 3;

    const int m0v = blockIdx.y * 128;
    const int n0  = blockIdx.x * 128;
    const int gate = n0 >> 9;
    a1 += (size_t)gate * a1_gate_stride;

    const int ncht = n1 + (UNITS / KC);   // total K chunks
    const int row  = tid >> 1;            // staging row 0..127
    const int half = tid & 1;

    float acc[2][8][4];
#pragma unroll
    for (int mt = 0; mt < 2; mt++)
#pragma unroll
        for (int nt = 0; nt < 8; nt++)
#pragma unroll
            for (int e = 0; e < 4; e++) acc[mt][nt][e] = 0.f;

    // issue chunk ic into buffer buf (A at buf*BUFSZ, B at buf*BUFSZ+TILE1)
    auto issue = [&](int ic, int buf) {
        const uint32_t abase = smem_base + buf * BUFSZ;
        const uint32_t bbase = abase + TILE1;
        const char* asrc;
        const char* bsrc;
        if (ic < n1) {
            asrc = (const char*)(a1 + (size_t)(m0v + row) * k1 + ic * KC);
            bsrc = (const char*)(bt1 + (size_t)(n0 + row) * k1 + ic * KC);
        } else {
            int ic2 = ic - n1;
            asrc = (const char*)(a2 + (size_t)(m0v + row) * UNITS + ic2 * KC);
            bsrc = (const char*)(bt2 + (size_t)(n0 + row) * UNITS + ic2 * KC);
        }
#pragma unroll
        for (int j = 0; j < 4; j++) {
            int seg = half * 4 + j;
            cpasync16(abase + row * 144 + seg * 16, asrc + seg * 16);
            cpasync16(bbase + row * 144 + seg * 16, bsrc + seg * 16);
        }
    };

    issue(0, 0);
    asm volatile("cp.async.commit_group;" ::: "memory");

    for (int ic = 0; ic < ncht; ++ic) {
        const int buf = ic & 1;
        if (ic + 1 < ncht) {
            issue(ic + 1, buf ^ 1);
            asm volatile("cp.async.commit_group;" ::: "memory");
            asm volatile("cp.async.wait_group 1;" ::: "memory");
        } else {
            asm volatile("cp.async.wait_group 0;" ::: "memory");
        }
        __syncthreads();

        const __nv_bfloat16* As = (const __nv_bfloat16*)(dsm + buf * BUFSZ);
        const __nv_bfloat16* Bs = (const __nv_bfloat16*)(dsm + buf * BUFSZ + TILE1);

#pragma unroll
        for (int ks = 0; ks < KC / 16; ks++) {
            const int kb = ks * 16 + gt * 2;
            uint32_t bf[8][2];
#pragma unroll
            for (int nt = 0; nt < 8; nt++) {
                const __nv_bfloat16* bp = Bs + (wn * 64 + nt * 8 + gq) * SSTRB + kb;
                bf[nt][0] = *(const uint32_t*)bp;
                bf[nt][1] = *(const uint32_t*)(bp + 8);
            }
#pragma unroll
            for (int mt = 0; mt < 2; mt++) {
                const int m = wm * 32 + mt * 16 + gq;
                const __nv_bfloat16* ap0 = As + m * SSTRB + kb;
                const __nv_bfloat16* ap1 = As + (m + 8) * SSTRB + kb;
                uint32_t a0 = *(const uint32_t*)ap0;
                uint32_t a1r = *(const uint32_t*)ap1;
                uint32_t a2r = *(const uint32_t*)(ap0 + 8);
                uint32_t a3 = *(const uint32_t*)(ap1 + 8);
#pragma unroll
                for (int nt = 0; nt < 8; nt++)
                    mma_bf16(acc[mt][nt], a0, a1r, a2r, a3, bf[nt][0], bf[nt][1]);
            }
        }
        __syncthreads();
    }

    // ---- epilogue: + bias, store z ----
#pragma unroll
    for (int mt = 0; mt < 2; mt++) {
        int row0 = m0v + wm * 32 + mt * 16 + gq;
#pragma unroll
        for (int nt = 0; nt < 8; nt++) {
            int col = n0 + wn * 64 + nt * 8 + gt * 2;
            float b0v = bias[col], b1v = bias[col + 1];
            float2 v0 = make_float2(acc[mt][nt][0] + b0v, acc[mt][nt][1] + b1v);
            float2 v1 = make_float2(acc[mt][nt][2] + b0v, acc[mt][nt][3] + b1v);
            *(float2*)(z + (size_t)row0 * NCOL + col) = v0;
            *(float2*)(z + (size_t)(row0 + 8) * NCOL + col) = v1;
        }
    }
}

// ---------------- LSTM pointwise ----------------
__device__ __forceinline__ float sigmoidf_(float x) {
    return 1.0f / (1.0f + expf(-x));
}

// layer0: update c0, emit h0 bf16 (unmasked) + 4 masked bf16 variants
__global__ void lstm_pointwise0(const float* __restrict__ z) {
    int idx = blockIdx.x * blockDim.x + threadIdx.x;
    if (idx >= B_ * UNITS) return;
    int b = idx / UNITS;
    int u = idx - b * UNITS;
    const float* zb = z + (size_t)b * NCOL;
    float ig = sigmoidf_(zb[u]);
    float fg = sigmoidf_(zb[UNITS + u]);
    float gg = tanhf(zb[2 * UNITS + u]);
    float og = sigmoidf_(zb[3 * UNITS + u]);
    float cn = fg * g_c0[idx] + ig * gg;
    g_c0[idx] = cn;
    float hn = og * tanhf(cn);
    g_h0b[idx] = __float2bfloat16(hn);
#pragma unroll
    for (int g = 0; g < 4; g++) {
        float m = g_m1[(size_t)g * B_ * UNITS + idx];
        g_h0m[(size_t)g * B_ * UNITS + idx] = __float2bfloat16(hn * m);
    }
}

// layer1: update c1, emit h1 bf16 + fp32
__global__ void lstm_pointwise1(const float* __restrict__ z) {
    int idx = blockIdx.x * blockDim.x + threadIdx.x;
    if (idx >= B_ * UNITS) return;
    int b = idx / UNITS;
    int u = idx - b * UNITS;
    const float* zb = z + (size_t)b * NCOL;
    float ig = sigmoidf_(zb[u]);
    float fg = sigmoidf_(zb[UNITS + u]);
    float gg = tanhf(zb[2 * UNITS + u]);
    float og = sigmoidf_(zb[3 * UNITS + u]);
    float cn = fg * g_c1[idx] + ig * gg;
    g_c1[idx] = cn;
    float hn = og * tanhf(cn);
    g_h1f[idx] = hn;
    g_h1b[idx] = __float2bfloat16(hn);
}

// ---------------- final projection ----------------
__global__ void out_kernel(const float* __restrict__ Wout,
                           const float* __restrict__ bout,
                           float* __restrict__ out) {
    int warps_per_block = blockDim.x / 32;
    int b = blockIdx.x * warps_per_block + (threadIdx.x >> 5);
    int lane = threadIdx.x & 31;
    if (b >= B_) return;
    float s = 0.f;
    for (int k = lane; k < UNITS; k += 32)
        s += g_h1f[b * UNITS + k] * Wout[k];
#pragma unroll
    for (int off = 16; off; off >>= 1)
        s += __shfl_down_sync(0xffffffffu, s, off);
    if (lane == 0)
        out[b] = sigmoidf_(s + bout[0]);
}

// ---------------- launch ----------------
extern "C" void kernel_launch(void* const* d_in, const int* in_sizes, int n_in,
                              void* d_out, int out_size) {
    const int*   inputs = (const int*)  d_in[0];
    const float* embed  = (const float*)d_in[1];
    const float* W0     = (const float*)d_in[2];
    const float* U0     = (const float*)d_in[3];
    const float* b0     = (const float*)d_in[4];
    const float* W1     = (const float*)d_in[5];
    const float* U1     = (const float*)d_in[6];
    const float* b1     = (const float*)d_in[7];
    const float* Wout   = (const float*)d_in[8];
    const float* bout   = (const float*)d_in[9];
    float* out = (float*)d_out;

    float *m0p, *m1p, *zp;
    __nv_bfloat16 *xmp, *h0bp, *h1bp, *h0mp, *wt0p, *ut0p, *wt1p, *ut1p;
    cudaGetSymbolAddress((void**)&m0p,  g_m0);
    cudaGetSymbolAddress((void**)&m1p,  g_m1);
    cudaGetSymbolAddress((void**)&zp,   g_z);
    cudaGetSymbolAddress((void**)&xmp,  g_xm);
    cudaGetSymbolAddress((void**)&h0bp, g_h0b);
    cudaGetSymbolAddress((void**)&h1bp, g_h1b);
    cudaGetSymbolAddress((void**)&h0mp, g_h0m);
    cudaGetSymbolAddress((void**)&wt0p, g_wt0);
    cudaGetSymbolAddress((void**)&ut0p, g_ut0);
    cudaGetSymbolAddress((void**)&wt1p, g_wt1);
    cudaGetSymbolAddress((void**)&ut1p, g_ut1);

    const int SMEM_GEMM = 2 * BUFSZ;   // 2 buffers x (A + B)
    cudaFuncSetAttribute(gate_gemm_bf16,
                         cudaFuncAttributeMaxDynamicSharedMemorySize, SMEM_GEMM);

    init_states_kernel<<<(B_ * UNITS + 255) / 256, 256>>>();

    {
        int S0 = 4 * B_ * EMB;
        int S1 = 4 * B_ * UNITS;
        mask_kernel<<<(S0 + 255) / 256, 256>>>(m0p, S0, 0);
        mask_kernel<<<(S1 + 255) / 256, 256>>>(m1p, S1, 1);
    }

    // precompute bf16 masked inputs and bf16 transposed weights
    {
        size_t tot = (size_t)T_ * 4 * B_ * EMBP;
        xm_kernel<<<(unsigned)((tot + 255) / 256), 256>>>(inputs, embed);
    }
    wtrans_kernel<<<((size_t)NCOL * EMBP  + 255) / 256, 256>>>(W0, wt0p, EMB,   EMBP);
    wtrans_kernel<<<((size_t)NCOL * UNITS + 255) / 256, 256>>>(U0, ut0p, UNITS, UNITS);
    wtrans_kernel<<<((size_t)NCOL * UNITS + 255) / 256, 256>>>(W1, wt1p, UNITS, UNITS);
    wtrans_kernel<<<((size_t)NCOL * UNITS + 255) / 256, 256>>>(U1, ut1p, UNITS, UNITS);

    dim3 ggrid(NCOL / 128, B_ / 128);   // (16, 32)
    int pw_blocks = (B_ * UNITS + 255) / 256;

    for (int t = 0; t < T_; ++t) {
        gate_gemm_bf16<<<ggrid, 256, SMEM_GEMM>>>(
            xmp + (size_t)t * 4 * B_ * EMBP, EMBP, EMBP / KC,
            (size_t)B_ * EMBP,
            h0bp, wt0p, ut0p, b0, zp);
        lstm_pointwise0<<<pw_blocks, 256>>>(zp);
        gate_gemm_bf16<<<ggrid, 256, SMEM_GEMM>>>(
            h0mp, UNITS, UNITS / KC,
            (size_t)B_ * UNITS,
            h1bp, wt1p, ut1p, b1, zp);
        lstm_pointwise1<<<pw_blocks, 256>>>(zp);
    }

    out_kernel<<<B_ / 8, 256>>>(Wout, bout, out);
}

// round 10
// speedup vs baseline: 4.8674x; 1.1743x over previous
#include <cuda_runtime.h>
#include <cuda_bf16.h>
#include <stdint.h>

// Problem constants
#define B_    4096
#define T_    80
#define EMB   100
#define EMBP  128    // EMB padded to k-chunk multiple
#define UNITS 512
#define NCOL  2048   // 4 gates * UNITS

// ---------------- device scratch (static allocations only) ----------------
__device__ float g_m0[4 * B_ * EMB];            // layer0 input dropout masks (fp32, for xm)
__device__ __nv_bfloat16 g_m1b[4 * B_ * UNITS]; // layer1 input dropout masks (bf16)
__device__ __nv_bfloat16 g_xm[(size_t)T_ * 4 * B_ * EMBP]; // x*m0, bf16, [t][g][b][k]
__device__ float g_c0[B_ * UNITS];
__device__ float g_c1[B_ * UNITS];
__device__ float g_h1f[B_ * UNITS];             // fp32 h1 for output projection
__device__ __nv_bfloat16 g_h0b[B_ * UNITS];     // h0 unmasked bf16 (U0 operand)
__device__ __nv_bfloat16 g_h1b[B_ * UNITS];     // h1 unmasked bf16 (U1 operand)
__device__ __nv_bfloat16 g_h0m[4 * B_ * UNITS]; // h0 * m1[g], bf16 (W1 operand)
__device__ float g_z [B_ * NCOL];
// bf16 weights, transposed to [n][k]
__device__ __nv_bfloat16 g_wt0[NCOL * EMBP];
__device__ __nv_bfloat16 g_ut0[NCOL * UNITS];
__device__ __nv_bfloat16 g_wt1[NCOL * UNITS];
__device__ __nv_bfloat16 g_ut1[NCOL * UNITS];

// ---------------- threefry2x32 (full 20 rounds) ----------------
__device__ __forceinline__ uint32_t rotl32(uint32_t x, int d) {
    return (x << d) | (x >> (32 - d));
}

__device__ __forceinline__ void tf2x32(uint32_t k0, uint32_t k1,
                                       uint32_t x0, uint32_t x1,
                                       uint32_t& o0, uint32_t& o1) {
    uint32_t ks0 = k0, ks1 = k1, ks2 = k0 ^ k1 ^ 0x1BD11BDAu;
    x0 += ks0; x1 += ks1;
#define TF_RND(r) { x0 += x1; x1 = rotl32(x1, r); x1 ^= x0; }
    TF_RND(13) TF_RND(15) TF_RND(26) TF_RND(6)
    x0 += ks1; x1 += ks2 + 1u;
    TF_RND(17) TF_RND(29) TF_RND(16) TF_RND(24)
    x0 += ks2; x1 += ks0 + 2u;
    TF_RND(13) TF_RND(15) TF_RND(26) TF_RND(6)
    x0 += ks0; x1 += ks1 + 3u;
    TF_RND(17) TF_RND(29) TF_RND(16) TF_RND(24)
    x0 += ks1; x1 += ks2 + 4u;
    TF_RND(13) TF_RND(15) TF_RND(26) TF_RND(6)
    x0 += ks2; x1 += ks0 + 5u;
#undef TF_RND
    o0 = x0; o1 = x1;
}

__device__ __forceinline__ float bits_to_mask(uint32_t bits) {
    float u = __uint_as_float((bits >> 9) | 0x3f800000u) - 1.0f;
    return (u < 0.8f) ? (1.0f / 0.8f) : 0.0f;
}

// ---------------- merged setup: masks + state init (launch #1) -------------
#define S0_ (4 * B_ * EMB)
#define S1_ (4 * B_ * UNITS)
#define S2_ (B_ * UNITS)

__global__ void setup_kernel() {
    size_t idx = (size_t)blockIdx.x * blockDim.x + threadIdx.x;
    if (idx < S0_) {
        uint32_t a0, a1, o0, o1;
        tf2x32(0u, 42u, 0u, 0u, a0, a1);           // split key 0
        tf2x32(a0, a1, 0u, (uint32_t)idx, o0, o1);
        g_m0[idx] = bits_to_mask(o0 ^ o1);
    } else if (idx < (size_t)S0_ + S1_) {
        uint32_t b0, b1, o0, o1;
        uint32_t j = (uint32_t)(idx - S0_);
        tf2x32(0u, 42u, 0u, 1u, b0, b1);           // split key 1
        tf2x32(b0, b1, 0u, j, o0, o1);
        g_m1b[j] = __float2bfloat16(bits_to_mask(o0 ^ o1));
    } else if (idx < (size_t)S0_ + S1_ + S2_) {
        int j = (int)(idx - S0_ - S1_);
        g_c0[j] = 0.f; g_c1[j] = 0.f; g_h1f[j] = 0.f;
        __nv_bfloat16 zb = __float2bfloat16(0.f);
        g_h0b[j] = zb; g_h1b[j] = zb;
#pragma unroll
        for (int g = 0; g < 4; g++) g_h0m[g * B_ * UNITS + j] = zb;
    }
}

// ---------------- precompute x*m0 in bf16: [t][g][b][k] (launch #2) --------
__global__ void xm_kernel(const int* __restrict__ inputs,
                          const float* __restrict__ embed) {
    size_t idx = (size_t)blockIdx.x * blockDim.x + threadIdx.x;
    if (idx >= (size_t)T_ * 4 * B_ * EMBP) return;
    int k = (int)(idx & 127);
    int b = (int)((idx >> 7) & 4095);
    int g = (int)((idx >> 19) & 3);
    int t = (int)(idx >> 21);
    float v = 0.f;
    if (k < EMB) {
        int tok = inputs[b * T_ + t];
        v = embed[(size_t)tok * EMB + k] * g_m0[((size_t)g * B_ + b) * EMB + k];
    }
    g_xm[idx] = __float2bfloat16(v);
}

// ---------------- merged weight transpose + bf16 (launch #3) ---------------
// layouts: wt0 [2048][EMBP] from W0[100][2048]; ut0/wt1/ut1 [2048][512]
#define WT0_N ((size_t)NCOL * EMBP)
#define WTU_N ((size_t)NCOL * UNITS)

__global__ void wtrans_all(const float* __restrict__ W0,
                           const float* __restrict__ U0,
                           const float* __restrict__ W1,
                           const float* __restrict__ U1) {
    size_t idx = (size_t)blockIdx.x * blockDim.x + threadIdx.x;
    if (idx < WT0_N) {
        int k = (int)(idx & (EMBP - 1));
        int n = (int)(idx >> 7);
        float v = (k < EMB) ? W0[(size_t)k * NCOL + n] : 0.f;
        g_wt0[idx] = __float2bfloat16(v);
        return;
    }
    size_t r = idx - WT0_N;
    if (r >= 3 * WTU_N) return;
    int sel = (int)(r / WTU_N);
    size_t j = r - (size_t)sel * WTU_N;
    int k = (int)(j & (UNITS - 1));
    int n = (int)(j >> 9);
    const float* src = (sel == 0) ? U0 : (sel == 1) ? W1 : U1;
    __nv_bfloat16* dst = (sel == 0) ? g_ut0 : (sel == 1) ? g_wt1 : g_ut1;
    dst[j] = __float2bfloat16(src[(size_t)k * NCOL + n]);
}

// ---------------- bf16 tensor-core gate GEMM, cp.async + ldmatrix ----------
// CTA tile 128x128, 256 threads (8 warps = 4M x 2N), warp tile 32x64,
// mma m16n8k16 bf16, K-chunk 64, smem stride 72 bf16 (144B rows,
// conflict-free for both cp.async staging and ldmatrix).
// SMEM per buffer: A tile (18432B) then B tile (18432B); buffer b at b*36864.
#define KC    64
#define SSTRB 72
#define TILE1 18432
#define BUFSZ (2 * TILE1)

__device__ __forceinline__ void cpasync16(uint32_t dst, const void* src) {
    asm volatile("cp.async.cg.shared.global [%0], [%1], 16;"
                 :: "r"(dst), "l"(src) : "memory");
}

__device__ __forceinline__ void ldmatrix4(uint32_t& r0, uint32_t& r1,
                                          uint32_t& r2, uint32_t& r3,
                                          uint32_t addr) {
    asm volatile("ldmatrix.sync.aligned.m8n8.x4.shared.b16 {%0,%1,%2,%3}, [%4];"
                 : "=r"(r0), "=r"(r1), "=r"(r2), "=r"(r3) : "r"(addr));
}

__device__ __forceinline__ void mma_bf16(float* c, uint32_t a0, uint32_t a1,
                                         uint32_t a2, uint32_t a3,
                                         uint32_t b0, uint32_t b1) {
    asm volatile(
        "mma.sync.aligned.m16n8k16.row.col.f32.bf16.bf16.f32 "
        "{%0,%1,%2,%3}, {%4,%5,%6,%7}, {%8,%9}, {%0,%1,%2,%3};"
        : "+f"(c[0]), "+f"(c[1]), "+f"(c[2]), "+f"(c[3])
        : "r"(a0), "r"(a1), "r"(a2), "r"(a3), "r"(b0), "r"(b1));
}

__global__ __launch_bounds__(256, 2)
void gate_gemm_bf16(const __nv_bfloat16* __restrict__ a1, int k1, int n1,
                    size_t a1_gate_stride,
                    const __nv_bfloat16* __restrict__ a2,   // [B][512]
                    const __nv_bfloat16* __restrict__ bt1,  // [2048][k1]
                    const __nv_bfloat16* __restrict__ bt2,  // [2048][512]
                    const float* __restrict__ bias,
                    float* __restrict__ z)
{
    extern __shared__ char dsm[];
    uint32_t smem_base;
    asm("{ .reg .u64 t; cvta.to.shared.u64 t, %1; cvt.u32.u64 %0, t; }"
        : "=r"(smem_base) : "l"(dsm));

    const int tid  = threadIdx.x;
    const int wid  = tid >> 5;
    const int lane = tid & 31;
    const int wm   = wid & 3;
    const int wn   = wid >> 2;
    const int gq   = lane >> 2;
    const int gt   = lane & 3;

    // ldmatrix per-thread addressing: 4 tiles per x4, lane i -> tile i/8, row i%8
    const int arow = lane & 7;
    const int asel = lane >> 3;
    // A x4 (mt, ks): tiles {(m,k0),(m+8,k0),(m,k8),(m+8,k8)}
    const uint32_t aoff = ((wm * 32 + (asel & 1) * 8 + arow) * SSTRB
                           + (asel >> 1) * 8) * 2;
    // B x4 (ks, ntp): tiles {(nt,k0),(nt,k8),(nt+1,k0),(nt+1,k8)}, rows = n
    const uint32_t boff = ((wn * 64 + (asel >> 1) * 8 + arow) * SSTRB
                           + (asel & 1) * 8) * 2;

    const int m0v = blockIdx.y * 128;
    const int n0  = blockIdx.x * 128;
    const int gate = n0 >> 9;
    a1 += (size_t)gate * a1_gate_stride;

    const int ncht = n1 + (UNITS / KC);
    const int row  = tid >> 1;
    const int half = tid & 1;

    float acc[2][8][4];
#pragma unroll
    for (int mt = 0; mt < 2; mt++)
#pragma unroll
        for (int nt = 0; nt < 8; nt++)
#pragma unroll
            for (int e = 0; e < 4; e++) acc[mt][nt][e] = 0.f;

    auto issue = [&](int ic, int buf) {
        const uint32_t abase = smem_base + buf * BUFSZ;
        const uint32_t bbase = abase + TILE1;
        const char* asrc;
        const char* bsrc;
        if (ic < n1) {
            asrc = (const char*)(a1 + (size_t)(m0v + row) * k1 + ic * KC);
            bsrc = (const char*)(bt1 + (size_t)(n0 + row) * k1 + ic * KC);
        } else {
            int ic2 = ic - n1;
            asrc = (const char*)(a2 + (size_t)(m0v + row) * UNITS + ic2 * KC);
            bsrc = (const char*)(bt2 + (size_t)(n0 + row) * UNITS + ic2 * KC);
        }
#pragma unroll
        for (int j = 0; j < 4; j++) {
            int seg = half * 4 + j;
            cpasync16(abase + row * 144 + seg * 16, asrc + seg * 16);
            cpasync16(bbase + row * 144 + seg * 16, bsrc + seg * 16);
        }
    };

    issue(0, 0);
    asm volatile("cp.async.commit_group;" ::: "memory");

    for (int ic = 0; ic < ncht; ++ic) {
        const int buf = ic & 1;
        if (ic + 1 < ncht) {
            issue(ic + 1, buf ^ 1);
            asm volatile("cp.async.commit_group;" ::: "memory");
            asm volatile("cp.async.wait_group 1;" ::: "memory");
        } else {
            asm volatile("cp.async.wait_group 0;" ::: "memory");
        }
        __syncthreads();

        const uint32_t As_u = smem_base + buf * BUFSZ;
        const uint32_t Bs_u = As_u + TILE1;

#pragma unroll
        for (int ks = 0; ks < KC / 16; ks++) {
            uint32_t bfr[8][2];
#pragma unroll
            for (int ntp = 0; ntp < 4; ntp++) {
                ldmatrix4(bfr[2 * ntp][0], bfr[2 * ntp][1],
                          bfr[2 * ntp + 1][0], bfr[2 * ntp + 1][1],
                          Bs_u + boff + (ntp * 16 * SSTRB + ks * 16) * 2);
            }
#pragma unroll
            for (int mt = 0; mt < 2; mt++) {
                uint32_t a0r, a1r, a2r, a3r;
                ldmatrix4(a0r, a1r, a2r, a3r,
                          As_u + aoff + (mt * 16 * SSTRB + ks * 16) * 2);
#pragma unroll
                for (int nt = 0; nt < 8; nt++)
                    mma_bf16(acc[mt][nt], a0r, a1r, a2r, a3r,
                             bfr[nt][0], bfr[nt][1]);
            }
        }
        __syncthreads();
    }

    // ---- epilogue: + bias, store z ----
#pragma unroll
    for (int mt = 0; mt < 2; mt++) {
        int row0 = m0v + wm * 32 + mt * 16 + gq;
#pragma unroll
        for (int nt = 0; nt < 8; nt++) {
            int col = n0 + wn * 64 + nt * 8 + gt * 2;
            float b0v = bias[col], b1v = bias[col + 1];
            float2 v0 = make_float2(acc[mt][nt][0] + b0v, acc[mt][nt][1] + b1v);
            float2 v1 = make_float2(acc[mt][nt][2] + b0v, acc[mt][nt][3] + b1v);
            *(float2*)(z + (size_t)row0 * NCOL + col) = v0;
            *(float2*)(z + (size_t)(row0 + 8) * NCOL + col) = v1;
        }
    }
}

// ---------------- LSTM pointwise (vectorized x2) ----------------
__device__ __forceinline__ float sigmoidf_(float x) {
    return 1.0f / (1.0f + expf(-x));
}

__global__ void lstm_pointwise0(const float* __restrict__ z) {
    int p = blockIdx.x * blockDim.x + threadIdx.x;
    if (p >= B_ * UNITS / 2) return;
    int b = p >> 8;               // UNITS/2 = 256 pairs per row
    int up = (p & 255) << 1;
    const float* zb = z + (size_t)b * NCOL;
    float2 zi = *(const float2*)(zb + up);
    float2 zf = *(const float2*)(zb + UNITS + up);
    float2 zg = *(const float2*)(zb + 2 * UNITS + up);
    float2 zo = *(const float2*)(zb + 3 * UNITS + up);
    int idx = b * UNITS + up;
    float2 c = *(const float2*)(g_c0 + idx);
    float cn0 = sigmoidf_(zf.x) * c.x + sigmoidf_(zi.x) * tanhf(zg.x);
    float cn1 = sigmoidf_(zf.y) * c.y + sigmoidf_(zi.y) * tanhf(zg.y);
    float hn0 = sigmoidf_(zo.x) * tanhf(cn0);
    float hn1 = sigmoidf_(zo.y) * tanhf(cn1);
    *(float2*)(g_c0 + idx) = make_float2(cn0, cn1);
    *(__nv_bfloat162*)(g_h0b + idx) = __floats2bfloat162_rn(hn0, hn1);
#pragma unroll
    for (int g = 0; g < 4; g++) {
        __nv_bfloat162 m = *(const __nv_bfloat162*)(g_m1b + (size_t)g * B_ * UNITS + idx);
        float v0 = hn0 * __bfloat162float(m.x);
        float v1 = hn1 * __bfloat162float(m.y);
        *(__nv_bfloat162*)(g_h0m + (size_t)g * B_ * UNITS + idx) =
            __floats2bfloat162_rn(v0, v1);
    }
}

__global__ void lstm_pointwise1(const float* __restrict__ z) {
    int p = blockIdx.x * blockDim.x + threadIdx.x;
    if (p >= B_ * UNITS / 2) return;
    int b = p >> 8;
    int up = (p & 255) << 1;
    const float* zb = z + (size_t)b * NCOL;
    float2 zi = *(const float2*)(zb + up);
    float2 zf = *(const float2*)(zb + UNITS + up);
    float2 zg = *(const float2*)(zb + 2 * UNITS + up);
    float2 zo = *(const float2*)(zb + 3 * UNITS + up);
    int idx = b * UNITS + up;
    float2 c = *(const float2*)(g_c1 + idx);
    float cn0 = sigmoidf_(zf.x) * c.x + sigmoidf_(zi.x) * tanhf(zg.x);
    float cn1 = sigmoidf_(zf.y) * c.y + sigmoidf_(zi.y) * tanhf(zg.y);
    float hn0 = sigmoidf_(zo.x) * tanhf(cn0);
    float hn1 = sigmoidf_(zo.y) * tanhf(cn1);
    *(float2*)(g_c1 + idx) = make_float2(cn0, cn1);
    *(float2*)(g_h1f + idx) = make_float2(hn0, hn1);
    *(__nv_bfloat162*)(g_h1b + idx) = __floats2bfloat162_rn(hn0, hn1);
}

// ---------------- final projection ----------------
__global__ void out_kernel(const float* __restrict__ Wout,
                           const float* __restrict__ bout,
                           float* __restrict__ out) {
    int warps_per_block = blockDim.x / 32;
    int b = blockIdx.x * warps_per_block + (threadIdx.x >> 5);
    int lane = threadIdx.x & 31;
    if (b >= B_) return;
    float s = 0.f;
    for (int k = lane; k < UNITS; k += 32)
        s += g_h1f[b * UNITS + k] * Wout[k];
#pragma unroll
    for (int off = 16; off; off >>= 1)
        s += __shfl_down_sync(0xffffffffu, s, off);
    if (lane == 0)
        out[b] = sigmoidf_(s + bout[0]);
}

// ---------------- launch ----------------
extern "C" void kernel_launch(void* const* d_in, const int* in_sizes, int n_in,
                              void* d_out, int out_size) {
    const int*   inputs = (const int*)  d_in[0];
    const float* embed  = (const float*)d_in[1];
    const float* W0     = (const float*)d_in[2];
    const float* U0     = (const float*)d_in[3];
    const float* b0     = (const float*)d_in[4];
    const float* W1     = (const float*)d_in[5];
    const float* U1     = (const float*)d_in[6];
    const float* b1     = (const float*)d_in[7];
    const float* Wout   = (const float*)d_in[8];
    const float* bout   = (const float*)d_in[9];
    float* out = (float*)d_out;

    float* zp;
    __nv_bfloat16 *xmp, *h0bp, *h1bp, *h0mp, *wt0p, *ut0p, *wt1p, *ut1p;
    cudaGetSymbolAddress((void**)&zp,   g_z);
    cudaGetSymbolAddress((void**)&xmp,  g_xm);
    cudaGetSymbolAddress((void**)&h0bp, g_h0b);
    cudaGetSymbolAddress((void**)&h1bp, g_h1b);
    cudaGetSymbolAddress((void**)&h0mp, g_h0m);
    cudaGetSymbolAddress((void**)&wt0p, g_wt0);
    cudaGetSymbolAddress((void**)&ut0p, g_ut0);
    cudaGetSymbolAddress((void**)&wt1p, g_wt1);
    cudaGetSymbolAddress((void**)&ut1p, g_ut1);

    const int SMEM_GEMM = 2 * BUFSZ;
    cudaFuncSetAttribute(gate_gemm_bf16,
                         cudaFuncAttributeMaxDynamicSharedMemorySize, SMEM_GEMM);

    // launch #1: masks + state init
    {
        size_t tot = (size_t)S0_ + S1_ + S2_;
        setup_kernel<<<(unsigned)((tot + 255) / 256), 256>>>();
    }
    // launch #2: masked embedded inputs
    {
        size_t tot = (size_t)T_ * 4 * B_ * EMBP;
        xm_kernel<<<(unsigned)((tot + 255) / 256), 256>>>(inputs, embed);
    }
    // launch #3: all weight transposes
    {
        size_t tot = WT0_N + 3 * WTU_N;
        wtrans_all<<<(unsigned)((tot + 255) / 256), 256>>>(W0, U0, W1, U1);
    }

    dim3 ggrid(NCOL / 128, B_ / 128);   // (16, 32)
    int pw_blocks = (B_ * UNITS / 2 + 255) / 256;

    // launches #4..: t=0 -> gemm0(#4), pw0(#5), gemm1(#6 <- ncu profile target)
    for (int t = 0; t < T_; ++t) {
        gate_gemm_bf16<<<ggrid, 256, SMEM_GEMM>>>(
            xmp + (size_t)t * 4 * B_ * EMBP, EMBP, EMBP / KC,
            (size_t)B_ * EMBP,
            h0bp, wt0p, ut0p, b0, zp);
        lstm_pointwise0<<<pw_blocks, 256>>>(zp);
        gate_gemm_bf16<<<ggrid, 256, SMEM_GEMM>>>(
            h0mp, UNITS, UNITS / KC,
            (size_t)B_ * UNITS,
            h1bp, wt1p, ut1p, b1, zp);
        lstm_pointwise1<<<pw_blocks, 256>>>(zp);
    }

    out_kernel<<<B_ / 8, 256>>>(Wout, bout, out);
}

// round 11
// speedup vs baseline: 5.1222x; 1.0523x over previous
#include <cuda_runtime.h>
#include <cuda_bf16.h>
#include <stdint.h>

// Problem constants
#define B_    4096
#define T_    80
#define EMB   100
#define EMBP  128
#define UNITS 512
#define NCOL  2048

// ---------------- device scratch ----------------
__device__ float g_m0[4 * B_ * EMB];
__device__ __nv_bfloat16 g_m1b[4 * B_ * UNITS];
__device__ __nv_bfloat16 g_xm[(size_t)T_ * 4 * B_ * EMBP]; // [t][g][b][k]
__device__ float g_c0[B_ * UNITS];
__device__ float g_c1[B_ * UNITS];
__device__ __nv_bfloat16 g_h0b[2][B_ * UNITS];  // ping-pong h0
__device__ __nv_bfloat16 g_h1b[2][B_ * UNITS];  // ping-pong h1
__device__ __nv_bfloat16 g_h0m[4 * B_ * UNITS]; // h0*m1[g]
// bf16 weights, transposed + gate-blocked columns: n' = (u/32)*128 + g*32 + (u%32)
__device__ __nv_bfloat16 g_wt0[NCOL * EMBP];
__device__ __nv_bfloat16 g_ut0[NCOL * UNITS];
__device__ __nv_bfloat16 g_wt1[NCOL * UNITS];
__device__ __nv_bfloat16 g_ut1[NCOL * UNITS];

// ---------------- threefry2x32 (full 20 rounds) ----------------
__device__ __forceinline__ uint32_t rotl32(uint32_t x, int d) {
    return (x << d) | (x >> (32 - d));
}

__device__ __forceinline__ void tf2x32(uint32_t k0, uint32_t k1,
                                       uint32_t x0, uint32_t x1,
                                       uint32_t& o0, uint32_t& o1) {
    uint32_t ks0 = k0, ks1 = k1, ks2 = k0 ^ k1 ^ 0x1BD11BDAu;
    x0 += ks0; x1 += ks1;
#define TF_RND(r) { x0 += x1; x1 = rotl32(x1, r); x1 ^= x0; }
    TF_RND(13) TF_RND(15) TF_RND(26) TF_RND(6)
    x0 += ks1; x1 += ks2 + 1u;
    TF_RND(17) TF_RND(29) TF_RND(16) TF_RND(24)
    x0 += ks2; x1 += ks0 + 2u;
    TF_RND(13) TF_RND(15) TF_RND(26) TF_RND(6)
    x0 += ks0; x1 += ks1 + 3u;
    TF_RND(17) TF_RND(29) TF_RND(16) TF_RND(24)
    x0 += ks1; x1 += ks2 + 4u;
    TF_RND(13) TF_RND(15) TF_RND(26) TF_RND(6)
    x0 += ks2; x1 += ks0 + 5u;
#undef TF_RND
    o0 = x0; o1 = x1;
}

__device__ __forceinline__ float bits_to_mask(uint32_t bits) {
    float u = __uint_as_float((bits >> 9) | 0x3f800000u) - 1.0f;
    return (u < 0.8f) ? (1.0f / 0.8f) : 0.0f;
}

#define S0_ (4 * B_ * EMB)
#define S1_ (4 * B_ * UNITS)
#define S2_ (B_ * UNITS)

__global__ void setup_kernel() {
    size_t idx = (size_t)blockIdx.x * blockDim.x + threadIdx.x;
    if (idx < S0_) {
        uint32_t a0, a1, o0, o1;
        tf2x32(0u, 42u, 0u, 0u, a0, a1);
        tf2x32(a0, a1, 0u, (uint32_t)idx, o0, o1);
        g_m0[idx] = bits_to_mask(o0 ^ o1);
    } else if (idx < (size_t)S0_ + S1_) {
        uint32_t b0, b1, o0, o1;
        uint32_t j = (uint32_t)(idx - S0_);
        tf2x32(0u, 42u, 0u, 1u, b0, b1);
        tf2x32(b0, b1, 0u, j, o0, o1);
        g_m1b[j] = __float2bfloat16(bits_to_mask(o0 ^ o1));
    } else if (idx < (size_t)S0_ + S1_ + S2_) {
        int j = (int)(idx - S0_ - S1_);
        g_c0[j] = 0.f; g_c1[j] = 0.f;
        __nv_bfloat16 zb = __float2bfloat16(0.f);
        g_h0b[0][j] = zb; g_h1b[0][j] = zb;
    }
}

// ---------------- precompute x*m0 in bf16: [t][g][b][k] ----------------
__global__ void xm_kernel(const int* __restrict__ inputs,
                          const float* __restrict__ embed) {
    size_t idx = (size_t)blockIdx.x * blockDim.x + threadIdx.x;
    if (idx >= (size_t)T_ * 4 * B_ * EMBP) return;
    int k = (int)(idx & 127);
    int b = (int)((idx >> 7) & 4095);
    int g = (int)((idx >> 19) & 3);
    int t = (int)(idx >> 21);
    float v = 0.f;
    if (k < EMB) {
        int tok = inputs[b * T_ + t];
        v = embed[(size_t)tok * EMB + k] * g_m0[((size_t)g * B_ + b) * EMB + k];
    }
    g_xm[idx] = __float2bfloat16(v);
}

// ---------------- weight transpose + bf16 + gate-blocked column reorder ----
// dst column n' = jtile*128 + g*32 + ul  <-  src column g*512 + jtile*32 + ul
#define WT0_N ((size_t)NCOL * EMBP)
#define WTU_N ((size_t)NCOL * UNITS)

__global__ void wtrans_all(const float* __restrict__ W0,
                           const float* __restrict__ U0,
                           const float* __restrict__ W1,
                           const float* __restrict__ U1) {
    size_t idx = (size_t)blockIdx.x * blockDim.x + threadIdx.x;
    if (idx < WT0_N) {
        int k  = (int)(idx & 127);
        int np = (int)(idx >> 7);
        int g = (np >> 5) & 3, ul = np & 31, j = np >> 7;
        int csrc = g * 512 + j * 32 + ul;
        float v = (k < EMB) ? W0[(size_t)k * NCOL + csrc] : 0.f;
        g_wt0[idx] = __float2bfloat16(v);
        return;
    }
    size_t r = idx - WT0_N;
    if (r >= 3 * WTU_N) return;
    int sel = (int)(r / WTU_N);
    size_t jdx = r - (size_t)sel * WTU_N;
    int k  = (int)(jdx & 511);
    int np = (int)(jdx >> 9);
    int g = (np >> 5) & 3, ul = np & 31, j = np >> 7;
    int csrc = g * 512 + j * 32 + ul;
    const float* src = (sel == 0) ? U0 : (sel == 1) ? W1 : U1;
    __nv_bfloat16* dst = (sel == 0) ? g_ut0 : (sel == 1) ? g_wt1 : g_ut1;
    dst[jdx] = __float2bfloat16(src[(size_t)k * NCOL + csrc]);
}

// ---------------- fused gate GEMM + LSTM cell epilogue ----------------
// CTA tile 128(b) x 128(n' = 4 gates x 32 u), 256 thr = 8 warps (2M x 4N:
// warp = (wm, gate)), warp tile 64x32, mma m16n8k16 bf16, K-chunk 32.
// SMEM stage: A = 4 gate planes (x-phase) or 1 plane (h-phase), B tile.
// Row = 64B data + 16B pad = 80B (conflict-free ldmatrix: (20r)%32 distinct).
#define KC2    32
#define ASTR   80
#define APLANE (128 * ASTR)        // 10240
#define ABYTES (4 * APLANE)        // 40960
#define STAGE  (ABYTES + APLANE)   // 51200
#define SMEMSZ (2 * STAGE)         // 102400

__device__ __forceinline__ void cpasync16(uint32_t dst, const void* src) {
    asm volatile("cp.async.cg.shared.global [%0], [%1], 16;"
                 :: "r"(dst), "l"(src) : "memory");
}

__device__ __forceinline__ void ldmatrix4(uint32_t& r0, uint32_t& r1,
                                          uint32_t& r2, uint32_t& r3,
                                          uint32_t addr) {
    asm volatile("ldmatrix.sync.aligned.m8n8.x4.shared.b16 {%0,%1,%2,%3}, [%4];"
                 : "=r"(r0), "=r"(r1), "=r"(r2), "=r"(r3) : "r"(addr));
}

__device__ __forceinline__ void mma_bf16(float* c, uint32_t a0, uint32_t a1,
                                         uint32_t a2, uint32_t a3,
                                         uint32_t b0, uint32_t b1) {
    asm volatile(
        "mma.sync.aligned.m16n8k16.row.col.f32.bf16.bf16.f32 "
        "{%0,%1,%2,%3}, {%4,%5,%6,%7}, {%8,%9}, {%0,%1,%2,%3};"
        : "+f"(c[0]), "+f"(c[1]), "+f"(c[2]), "+f"(c[3])
        : "r"(a0), "r"(a1), "r"(a2), "r"(a3), "r"(b0), "r"(b1));
}

__device__ __forceinline__ float tanh_ap(float x) {
    float r;
    asm("tanh.approx.f32 %0, %1;" : "=f"(r) : "f"(x));
    return r;
}
__device__ __forceinline__ float sig_ap(float x) {
    return 0.5f * tanh_ap(0.5f * x) + 0.5f;
}

__global__ __launch_bounds__(256, 2)
void gate_gemm_fused(const __nv_bfloat16* __restrict__ a1, int k1, int nch1,
                     size_t plane_stride,
                     const __nv_bfloat16* __restrict__ a2,   // h prev [B][512]
                     const __nv_bfloat16* __restrict__ bt1,  // [2048][k1]
                     const __nv_bfloat16* __restrict__ bt2,  // [2048][512]
                     const float* __restrict__ bias,         // [2048] gate-major
                     float* __restrict__ cst,
                     __nv_bfloat16* __restrict__ hout,
                     __nv_bfloat16* __restrict__ hmout,      // null for layer1
                     const __nv_bfloat16* __restrict__ m1b)
{
    extern __shared__ char dsm[];
    uint32_t smem_base;
    asm("{ .reg .u64 t; cvta.to.shared.u64 t, %1; cvt.u32.u64 %0, t; }"
        : "=r"(smem_base) : "l"(dsm));

    const int tid  = threadIdx.x;
    const int wid  = tid >> 5;
    const int lane = tid & 31;
    const int wm   = wid >> 2;        // 0..1, 64-row M block
    const int gate = wid & 3;         // this warp's gate
    const int gq   = lane >> 2;
    const int gt   = lane & 3;
    const int arow = lane & 7;
    const int asel = lane >> 3;

    const int m0v = blockIdx.y * 128;
    const int n0  = blockIdx.x * 128;   // reordered column space
    const int u0  = blockIdx.x * 32;

    const int ncht = nch1 + UNITS / KC2;

    float acc[4][4][4];
#pragma unroll
    for (int mt = 0; mt < 4; mt++)
#pragma unroll
        for (int nt = 0; nt < 4; nt++)
#pragma unroll
            for (int e = 0; e < 4; e++) acc[mt][nt][e] = 0.f;

    auto issue = [&](int ic, int buf) {
        const uint32_t base = smem_base + buf * STAGE;
        if (ic < nch1) {
            // x phase: 4 gate planes of A + B
#pragma unroll
            for (int i = 0; i < 8; i++) {
                int idx = tid + i * 256;
                int p = idx >> 9, r = (idx >> 2) & 127, s = idx & 3;
                cpasync16(base + p * APLANE + r * ASTR + s * 16,
                          (const char*)(a1 + (size_t)p * plane_stride
                                        + (size_t)(m0v + r) * k1
                                        + (size_t)ic * KC2) + s * 16);
            }
#pragma unroll
            for (int i = 0; i < 2; i++) {
                int idx = tid + i * 256;
                int r = idx >> 2, s = idx & 3;
                cpasync16(base + ABYTES + r * ASTR + s * 16,
                          (const char*)(bt1 + (size_t)(n0 + r) * k1
                                        + (size_t)ic * KC2) + s * 16);
            }
        } else {
            int ic2 = ic - nch1;
#pragma unroll
            for (int i = 0; i < 2; i++) {
                int idx = tid + i * 256;
                int r = idx >> 2, s = idx & 3;
                cpasync16(base + r * ASTR + s * 16,
                          (const char*)(a2 + (size_t)(m0v + r) * UNITS
                                        + (size_t)ic2 * KC2) + s * 16);
                cpasync16(base + ABYTES + r * ASTR + s * 16,
                          (const char*)(bt2 + (size_t)(n0 + r) * UNITS
                                        + (size_t)ic2 * KC2) + s * 16);
            }
        }
    };

    issue(0, 0);
    asm volatile("cp.async.commit_group;" ::: "memory");

    for (int ic = 0; ic < ncht; ++ic) {
        const int buf = ic & 1;
        if (ic + 1 < ncht) {
            issue(ic + 1, buf ^ 1);
            asm volatile("cp.async.commit_group;" ::: "memory");
            asm volatile("cp.async.wait_group 1;" ::: "memory");
        } else {
            asm volatile("cp.async.wait_group 0;" ::: "memory");
        }
        __syncthreads();

        const uint32_t stg = smem_base + buf * STAGE;
        const uint32_t plane_off = (ic < nch1) ? (uint32_t)(gate * APLANE) : 0u;

#pragma unroll
        for (int ks = 0; ks < 2; ks++) {
            uint32_t bfr[4][2];
#pragma unroll
            for (int ntp = 0; ntp < 2; ntp++) {
                uint32_t r0, r1, r2, r3;
                ldmatrix4(r0, r1, r2, r3,
                    stg + ABYTES
                        + (uint32_t)((gate * 32 + ntp * 16 + (asel >> 1) * 8 + arow) * ASTR)
                        + (uint32_t)((ks * 16 + (asel & 1) * 8) * 2));
                bfr[2 * ntp][0] = r0; bfr[2 * ntp][1] = r1;
                bfr[2 * ntp + 1][0] = r2; bfr[2 * ntp + 1][1] = r3;
            }
#pragma unroll
            for (int mt = 0; mt < 4; mt++) {
                uint32_t a0r, a1r, a2r, a3r;
                ldmatrix4(a0r, a1r, a2r, a3r,
                    stg + plane_off
                        + (uint32_t)((wm * 64 + mt * 16 + (asel & 1) * 8 + arow) * ASTR)
                        + (uint32_t)((ks * 16 + (asel >> 1) * 8) * 2));
#pragma unroll
                for (int nt = 0; nt < 4; nt++)
                    mma_bf16(acc[mt][nt], a0r, a1r, a2r, a3r,
                             bfr[nt][0], bfr[nt][1]);
            }
        }
        __syncthreads();
    }

    // ---- epilogue 1: acc -> smem z tile [128][132] fp32 ----
    float* zs = (float*)dsm;
#pragma unroll
    for (int mt = 0; mt < 4; mt++) {
        int row0 = wm * 64 + mt * 16 + gq;
#pragma unroll
        for (int nt = 0; nt < 4; nt++) {
            int col = gate * 32 + nt * 8 + gt * 2;
            zs[row0 * 132 + col]     = acc[mt][nt][0];
            zs[row0 * 132 + col + 1] = acc[mt][nt][1];
            zs[(row0 + 8) * 132 + col]     = acc[mt][nt][2];
            zs[(row0 + 8) * 132 + col + 1] = acc[mt][nt][3];
        }
    }
    __syncthreads();

    // ---- epilogue 2: LSTM cell update for 128 b x 32 u ----
#pragma unroll 4
    for (int pass = 0; pass < 16; pass++) {
        int cell = pass * 256 + tid;
        int bl = cell >> 5;
        int ul = cell & 31;
        float zi = zs[bl * 132 + ul]      + bias[u0 + ul];
        float zf = zs[bl * 132 + 32 + ul] + bias[512 + u0 + ul];
        float zg = zs[bl * 132 + 64 + ul] + bias[1024 + u0 + ul];
        float zo = zs[bl * 132 + 96 + ul] + bias[1536 + u0 + ul];
        float ig = sig_ap(zi);
        float fg = sig_ap(zf);
        float gg = tanh_ap(zg);
        float og = sig_ap(zo);
        size_t idx = (size_t)(m0v + bl) * UNITS + u0 + ul;
        float cn = fg * cst[idx] + ig * gg;
        cst[idx] = cn;
        float hn = og * tanh_ap(cn);
        hout[idx] = __float2bfloat16(hn);
        if (hmout) {
#pragma unroll
            for (int g4 = 0; g4 < 4; g4++) {
                float m = __bfloat162float(m1b[(size_t)g4 * B_ * UNITS + idx]);
                hmout[(size_t)g4 * B_ * UNITS + idx] = __float2bfloat16(hn * m);
            }
        }
    }
}

// ---------------- final projection (reads bf16 h1) ----------------
__global__ void out_kernel(const float* __restrict__ Wout,
                           const float* __restrict__ bout,
                           float* __restrict__ out) {
    int warps_per_block = blockDim.x / 32;
    int b = blockIdx.x * warps_per_block + (threadIdx.x >> 5);
    int lane = threadIdx.x & 31;
    if (b >= B_) return;
    float s = 0.f;
    for (int k = lane; k < UNITS; k += 32)
        s += __bfloat162float(g_h1b[0][b * UNITS + k]) * Wout[k];
#pragma unroll
    for (int off = 16; off; off >>= 1)
        s += __shfl_down_sync(0xffffffffu, s, off);
    if (lane == 0)
        out[b] = 1.0f / (1.0f + expf(-(s + bout[0])));
}

// ---------------- launch ----------------
extern "C" void kernel_launch(void* const* d_in, const int* in_sizes, int n_in,
                              void* d_out, int out_size) {
    const int*   inputs = (const int*)  d_in[0];
    const float* embed  = (const float*)d_in[1];
    const float* W0     = (const float*)d_in[2];
    const float* U0     = (const float*)d_in[3];
    const float* b0     = (const float*)d_in[4];
    const float* W1     = (const float*)d_in[5];
    const float* U1     = (const float*)d_in[6];
    const float* b1     = (const float*)d_in[7];
    const float* Wout   = (const float*)d_in[8];
    const float* bout   = (const float*)d_in[9];
    float* out = (float*)d_out;

    float *c0p, *c1p;
    __nv_bfloat16 *xmp, *h0mp, *m1bp, *wt0p, *ut0p, *wt1p, *ut1p;
    __nv_bfloat16 (*h0bp)[B_ * UNITS], (*h1bp)[B_ * UNITS];
    cudaGetSymbolAddress((void**)&c0p,  g_c0);
    cudaGetSymbolAddress((void**)&c1p,  g_c1);
    cudaGetSymbolAddress((void**)&xmp,  g_xm);
    cudaGetSymbolAddress((void**)&h0bp, g_h0b);
    cudaGetSymbolAddress((void**)&h1bp, g_h1b);
    cudaGetSymbolAddress((void**)&h0mp, g_h0m);
    cudaGetSymbolAddress((void**)&m1bp, g_m1b);
    cudaGetSymbolAddress((void**)&wt0p, g_wt0);
    cudaGetSymbolAddress((void**)&ut0p, g_ut0);
    cudaGetSymbolAddress((void**)&wt1p, g_wt1);
    cudaGetSymbolAddress((void**)&ut1p, g_ut1);

    cudaFuncSetAttribute(gate_gemm_fused,
                         cudaFuncAttributeMaxDynamicSharedMemorySize, SMEMSZ);

    {
        size_t tot = (size_t)S0_ + S1_ + S2_;
        setup_kernel<<<(unsigned)((tot + 255) / 256), 256>>>();
    }
    {
        size_t tot = (size_t)T_ * 4 * B_ * EMBP;
        xm_kernel<<<(unsigned)((tot + 255) / 256), 256>>>(inputs, embed);
    }
    {
        size_t tot = WT0_N + 3 * WTU_N;
        wtrans_all<<<(unsigned)((tot + 255) / 256), 256>>>(W0, U0, W1, U1);
    }

    dim3 ggrid(16, 32);   // (u-tiles, m-tiles)

    for (int t = 0; t < T_; ++t) {
        int rp = t & 1, wp = rp ^ 1;
        // layer 0: x-part = 4-plane masked embeddings, h-part = h0[rp]
        gate_gemm_fused<<<ggrid, 256, SMEMSZ>>>(
            xmp + (size_t)t * 4 * B_ * EMBP, EMBP, EMBP / KC2,
            (size_t)B_ * EMBP,
            h0bp[rp], wt0p, ut0p, b0,
            c0p, h0bp[wp], h0mp, m1bp);
        // layer 1: x-part = 4-plane masked h0 (just written), h-part = h1[rp]
        gate_gemm_fused<<<ggrid, 256, SMEMSZ>>>(
            h0mp, UNITS, UNITS / KC2,
            (size_t)B_ * UNITS,
            h1bp[rp], wt1p, ut1p, b1,
            c1p, h1bp[wp], (__nv_bfloat16*)nullptr, (const __nv_bfloat16*)nullptr);
    }

    out_kernel<<<B_ / 8, 256>>>(Wout, bout, out);
}